// round 2
// baseline (speedup 1.0000x reference)
#include <cuda_runtime.h>

#define BB 64
#define LL 25
#define FF 128
#define PP 10000

// ---------------- device scratch (no dynamic allocation allowed) ----------------
__device__ float g_inputs[BB*LL*FF];
__device__ float g_q[BB*LL*FF];
__device__ float g_k[BB*LL*FF];
__device__ float g_v[BB*LL*FF];
__device__ float g_attn[BB*LL*FF];
__device__ float g_ds[BB*LL*LL];
__device__ float g_dt[BB*LL*LL];
__device__ float g_tint[BB*LL];
// 0: ds max, 1: ds min, 2: dt max, 3: dt min,
// 4: interval_s max, 5: interval_s min, 6: tint max, 7: tint min
// All reduced values are >= 0, so int-bit compare == float compare.
__device__ int g_stats[8];

__device__ __forceinline__ void redMax(float v, int slot) {
    #pragma unroll
    for (int o = 16; o; o >>= 1) v = fmaxf(v, __shfl_xor_sync(0xffffffffu, v, o));
    if ((threadIdx.x & 31) == 0) atomicMax(&g_stats[slot], __float_as_int(v));
}
__device__ __forceinline__ void redMin(float v, int slot) {
    #pragma unroll
    for (int o = 16; o; o >>= 1) v = fminf(v, __shfl_xor_sync(0xffffffffu, v, o));
    if ((threadIdx.x & 31) == 0) atomicMin(&g_stats[slot], __float_as_int(v));
}

// packed fp32x2 FMA (Blackwell; 2x FFMA throughput, only reachable via PTX)
__device__ __forceinline__ void ffma2(unsigned long long& d, unsigned long long a, unsigned long long b) {
    asm("fma.rn.f32x2 %0, %1, %2, %0;" : "+l"(d) : "l"(a), "l"(b));
}

// ---------------- kernel 0: init reduction slots (must re-run every replay) ----
__global__ void k_init() {
    int t = threadIdx.x;
    if (t < 8) g_stats[t] = (t & 1) ? 0x7F800000 : 0;  // min slots = +inf, max slots = 0 (all data >= 0)
}

// ---------------- kernel 1: embeddings + pairwise ds/dt + time_interval -------
__global__ void k_prep(const int* __restrict__ user, const int* __restrict__ poi,
                       const int* __restrict__ tod, const int* __restrict__ dow,
                       const float* __restrict__ lat, const float* __restrict__ lon,
                       const float* __restrict__ ut,
                       const float* __restrict__ ue, const float* __restrict__ pe,
                       const float* __restrict__ te, const float* __restrict__ de) {
    int b = blockIdx.x, tid = threadIdx.x;

    for (int o = tid; o < LL*FF; o += blockDim.x) {
        int l = o >> 7, f = o & 127;
        int base = b*LL + l;
        g_inputs[b*LL*FF + o] = ue[(size_t)user[base]*FF + f] + pe[(size_t)poi[base]*FF + f]
                              + te[tod[base]*FF + f] + de[dow[base]*FF + f];
    }

    const float rad = 0.017453292519943295f;
    const float INF = __int_as_float(0x7F800000);
    float mxs = 0.f, mns = INF, mxt = 0.f, mnt = INF;
    for (int e = tid; e < LL*LL; e += blockDim.x) {
        int i = e / LL, j = e % LL;
        float la1 = lat[b*LL+i], lo1 = lon[b*LL+i];
        float la2 = lat[b*LL+j], lo2 = lon[b*LL+j];
        float a = 0.5f - 0.5f*cosf((la2-la1)*rad)
                + cosf(la1*rad)*cosf(la2*rad)*(1.0f - cosf((lo2-lo1)*rad))*0.5f;
        float ds = 12742.0f * asinf(sqrtf(a));
        float dt = fabsf(ut[b*LL+i] - ut[b*LL+j]);
        g_ds[b*LL*LL + e] = ds;
        g_dt[b*LL*LL + e] = dt;
        mxs = fmaxf(mxs, ds); mns = fminf(mns, ds);
        mxt = fmaxf(mxt, dt); mnt = fminf(mnt, dt);
    }
    float mxi = 0.f, mni = INF;
    if (tid < LL) {
        float ti = (tid == 0) ? 0.f : fabsf(ut[b*LL+tid] - ut[b*LL+tid-1]);
        g_tint[b*LL + tid] = ti;
        mxi = ti; mni = ti;
    }
    redMax(mxs, 0); redMin(mns, 1);
    redMax(mxt, 2); redMin(mnt, 3);
    redMax(mxi, 6); redMin(mni, 7);
}

// ---------------- kernel 2: scan distance_matrix[poi] for max/min -------------
__global__ void k_scan(const int* __restrict__ poi, const float* __restrict__ dist) {
    int m = blockIdx.x;            // one block per (b,l) row: 1600 blocks
    int row = poi[m];
    const float4* d4 = (const float4*)(dist + (size_t)row * PP);
    float mx = 0.f, mn = __int_as_float(0x7F800000);
    for (int c = threadIdx.x; c < PP/4; c += blockDim.x) {
        float4 v = d4[c];
        mx = fmaxf(mx, fmaxf(fmaxf(v.x, v.y), fmaxf(v.z, v.w)));
        mn = fminf(mn, fminf(fminf(v.x, v.y), fminf(v.z, v.w)));
    }
    redMax(mx, 4); redMin(mn, 5);
}

// ---------------- kernel 3: Q,K,V projections ---------------------------------
__global__ void k_qkv(const float* __restrict__ Wq, const float* __restrict__ bq,
                      const float* __restrict__ Wk, const float* __restrict__ bk,
                      const float* __restrict__ Wv, const float* __restrict__ bv) {
    int b = blockIdx.x, tid = threadIdx.x;
    __shared__ float in_s[LL*FF];
    for (int o = tid; o < LL*FF; o += blockDim.x) in_s[o] = g_inputs[b*LL*FF + o];
    __syncthreads();
    const int F4 = FF/4;
    for (int o = tid; o < 3*LL*F4; o += blockDim.x) {
        int m = o / (LL*F4);
        int r = o % (LL*F4);
        int l = r / F4, f4 = r % F4;
        const float*  W  = (m == 0) ? Wq : (m == 1) ? Wk : Wv;
        const float*  bb = (m == 0) ? bq : (m == 1) ? bk : bv;
        const float4* W4 = (const float4*)W;
        float4 acc = ((const float4*)bb)[f4];
        #pragma unroll 4
        for (int g = 0; g < FF; ++g) {
            float  a = in_s[l*FF + g];
            float4 w = W4[g*F4 + f4];
            acc.x += a*w.x; acc.y += a*w.y; acc.z += a*w.z; acc.w += a*w.w;
        }
        float* out = (m == 0) ? g_q : (m == 1) ? g_k : g_v;
        ((float4*)out)[b*LL*F4 + r] = acc;
    }
}

// ---------------- kernel 4: per-batch attention -------------------------------
__global__ void k_att() {
    int b = blockIdx.x, tid = threadIdx.x;
    __shared__ float qs[LL*FF], ks[LL*FF], vs[LL*FF], aw[LL*LL];
    for (int o = tid; o < LL*FF; o += blockDim.x) {
        qs[o] = g_q[b*LL*FF + o];
        ks[o] = g_k[b*LL*FF + o];
        vs[o] = g_v[b*LL*FF + o];
    }
    __syncthreads();
    float su = __int_as_float(g_stats[0]), sl = __int_as_float(g_stats[1]);
    float tu = __int_as_float(g_stats[2]), tl = __int_as_float(g_stats[3]);
    float nis = -1.0f/(su - sl), nit = -1.0f/(tu - tl);
    for (int e = tid; e < LL*LL; e += blockDim.x) {
        int i = e / LL, j = e % LL;
        const float4* q4 = (const float4*)(qs + i*FF);
        const float4* k4 = (const float4*)(ks + j*FF);
        float s = 0.f;
        #pragma unroll
        for (int f = 0; f < FF/4; ++f) {
            float4 a = q4[f], c = k4[f];
            s += a.x*c.x + a.y*c.y + a.z*c.z + a.w*c.w;
        }
        float delta = 0.5f*(__expf(g_ds[b*LL*LL + e]*nis) + __expf(g_dt[b*LL*LL + e]*nit));
        aw[e] = s + delta;
    }
    __syncthreads();
    if (tid < LL) {
        float m = -1e30f;
        #pragma unroll
        for (int j = 0; j < LL; ++j) m = fmaxf(m, aw[tid*LL + j]);
        float tmp[LL], sum = 0.f;
        #pragma unroll
        for (int j = 0; j < LL; ++j) { float e = __expf(aw[tid*LL + j] - m); tmp[j] = e; sum += e; }
        float inv = 1.0f / sum;
        #pragma unroll
        for (int j = 0; j < LL; ++j) aw[tid*LL + j] = tmp[j] * inv;
    }
    __syncthreads();
    for (int o = tid; o < LL*FF; o += blockDim.x) {
        int i = o >> 7, f = o & 127;
        float s = 0.f;
        #pragma unroll
        for (int j = 0; j < LL; ++j) s += aw[i*LL + j] * vs[j*FF + f];
        g_attn[b*LL*FF + o] = s;
    }
}

// ---------------- kernel 5: fused candidate scoring (the big one) -------------
// pre[b,p] = b_val + sum_l (0.5*w_l*exp(-dist[poi_bl,p]/Ds) + 0.5*w_l*Et_bl) * <attn_bl, poi_emb_p>
__global__ __launch_bounds__(256) void k_final(const float* __restrict__ poi_emb,
                                               const float* __restrict__ dist,
                                               const int* __restrict__ poi,
                                               const float* __restrict__ w_val,
                                               const float* __restrict__ b_val,
                                               float* __restrict__ out, int out_size) {
    int b = blockIdx.y, tid = threadIdx.x;
    int p = blockIdx.x * 256 + tid;
    __shared__ __align__(16) float A[LL*FF];
    __shared__ int   idxs[LL];
    __shared__ float sa[LL], se[LL];
    for (int o = tid; o < LL*FF; o += 256) A[o] = g_attn[b*LL*FF + o];
    if (tid < LL) {
        idxs[tid] = poi[b*LL + tid];
        float Dt = __int_as_float(g_stats[6]) - __int_as_float(g_stats[7]);
        float s = 0.5f * w_val[tid];
        sa[tid] = s;
        se[tid] = s * __expf(-g_tint[b*LL + tid] / Dt);
    }
    __syncthreads();
    if (p >= PP) return;

    float nis = -1.0f / (__int_as_float(g_stats[4]) - __int_as_float(g_stats[5]));

    unsigned long long acc[LL];
    #pragma unroll
    for (int l = 0; l < LL; ++l) acc[l] = 0ull;

    const ulonglong2* W2 = (const ulonglong2*)(poi_emb + (size_t)p * FF);  // 32 entries of 4 floats
    const ulonglong2* A2 = (const ulonglong2*)A;
    #pragma unroll 2
    for (int f4 = 0; f4 < FF/4; ++f4) {
        ulonglong2 w = W2[f4];
        #pragma unroll
        for (int l = 0; l < LL; ++l) {
            ulonglong2 a = A2[l*(FF/4) + f4];
            ffma2(acc[l], a.x, w.x);
            ffma2(acc[l], a.y, w.y);
        }
    }

    float pre = b_val[0];
    #pragma unroll
    for (int l = 0; l < LL; ++l) {
        unsigned long long v = acc[l];
        float g = __uint_as_float((unsigned)v) + __uint_as_float((unsigned)(v >> 32));
        float es = __expf(dist[(size_t)idxs[l]*PP + p] * nis);
        pre += (sa[l]*es + se[l]) * g;
    }
    int n = b*PP + p;
    out[n] = pre;
    if (out_size >= 2*BB*PP) out[BB*PP + n] = pre;   // reference returns (pre, pre)
}

// ---------------- launch ------------------------------------------------------
extern "C" void kernel_launch(void* const* d_in, const int* in_sizes, int n_in,
                              void* d_out, int out_size) {
    const int*   user  = (const int*)d_in[0];
    const int*   poi   = (const int*)d_in[1];
    // d_in[2] = cat (unused by reference)
    const float* lat   = (const float*)d_in[3];
    const float* lon   = (const float*)d_in[4];
    const int*   tod   = (const int*)d_in[5];
    const int*   dow   = (const int*)d_in[6];
    const float* ut    = (const float*)d_in[7];
    const float* ue    = (const float*)d_in[8];
    const float* pe    = (const float*)d_in[9];
    const float* te    = (const float*)d_in[10];
    const float* de    = (const float*)d_in[11];
    const float* Wq    = (const float*)d_in[12];
    const float* bq    = (const float*)d_in[13];
    const float* Wk    = (const float*)d_in[14];
    const float* bk    = (const float*)d_in[15];
    const float* Wv    = (const float*)d_in[16];
    const float* bv    = (const float*)d_in[17];
    const float* w_val = (const float*)d_in[18];
    const float* b_val = (const float*)d_in[19];
    const float* dist  = (const float*)d_in[20];
    float* out = (float*)d_out;

    k_init<<<1, 32>>>();
    k_prep<<<BB, 256>>>(user, poi, tod, dow, lat, lon, ut, ue, pe, te, de);
    k_scan<<<BB*LL, 256>>>(poi, dist);
    k_qkv<<<BB, 256>>>(Wq, bq, Wk, bk, Wv, bv);
    k_att<<<BB, 256>>>();
    k_final<<<dim3((PP + 255)/256, BB), 256>>>(pe, dist, poi, w_val, b_val, out, out_size);
}

// round 4
// speedup vs baseline: 1.1975x; 1.1975x over previous
#include <cuda_runtime.h>

#define BB 64
#define LL 25
#define FF 128
#define PP 10000
#define GB 3          // batches per k_final block

// ---------------- device scratch ----------------
__device__ float g_q[BB*LL*FF];
__device__ float g_k[BB*LL*FF];
__device__ float g_v[BB*LL*FF];
__device__ float g_attn[BB*LL*FF];
__device__ float g_ds[BB*LL*LL];
__device__ float g_dt[BB*LL*LL];
__device__ float g_tint[BB*LL];
// 0: ds max, 1: ds min, 2: dt max, 3: dt min,
// 4: interval_s max, 5: interval_s min, 6: tint max, 7: tint min
__device__ int g_stats[8];

__device__ __forceinline__ void redMax(float v, int slot) {
    #pragma unroll
    for (int o = 16; o; o >>= 1) v = fmaxf(v, __shfl_xor_sync(0xffffffffu, v, o));
    if ((threadIdx.x & 31) == 0) atomicMax(&g_stats[slot], __float_as_int(v));
}
__device__ __forceinline__ void redMin(float v, int slot) {
    #pragma unroll
    for (int o = 16; o; o >>= 1) v = fminf(v, __shfl_xor_sync(0xffffffffu, v, o));
    if ((threadIdx.x & 31) == 0) atomicMin(&g_stats[slot], __float_as_int(v));
}

// packed fp32x2 FMA (Blackwell FFMA2, only reachable via PTX)
__device__ __forceinline__ void ffma2(unsigned long long& d, unsigned long long a, unsigned long long b) {
    asm("fma.rn.f32x2 %0, %1, %2, %0;" : "+l"(d) : "l"(a), "l"(b));
}
__device__ __forceinline__ unsigned long long pack2(float x, float y) {
    unsigned long long r; asm("mov.b64 %0, {%1, %2};" : "=l"(r) : "f"(x), "f"(y)); return r;
}
__device__ __forceinline__ float lo2(unsigned long long v) { return __uint_as_float((unsigned)v); }
__device__ __forceinline__ float hi2(unsigned long long v) { return __uint_as_float((unsigned)(v >> 32)); }

// ---------------- kernel 0: init reduction slots -------------------------------
__global__ void k_init() {
    int t = threadIdx.x;
    if (t < 8) g_stats[t] = (t & 1) ? 0x7F800000 : 0;
}

// ---------------- kernel 1: embeddings + ds/dt + tint + fused QKV --------------
// 384 threads: thread t -> matrix m = t>>7 (Q/K/V), column f = t&127.
// Inputs stored TRANSPOSED in smem: inT[g][l], row stride 28 floats so one
// broadcast LDS.128 yields 4 consecutive l-values (as two f32x2 pairs).
__global__ __launch_bounds__(384) void k_prep_qkv(
        const int* __restrict__ user, const int* __restrict__ poi,
        const int* __restrict__ tod, const int* __restrict__ dow,
        const float* __restrict__ lat, const float* __restrict__ lon,
        const float* __restrict__ ut,
        const float* __restrict__ ue, const float* __restrict__ pe,
        const float* __restrict__ te, const float* __restrict__ de,
        const float* __restrict__ Wq, const float* __restrict__ bq,
        const float* __restrict__ Wk, const float* __restrict__ bk,
        const float* __restrict__ Wv, const float* __restrict__ bv) {
    __shared__ __align__(16) float inT[FF*28];
    int b = blockIdx.x, tid = threadIdx.x;

    // embeddings -> transposed smem
    for (int o = tid; o < LL*FF; o += 384) {
        int l = o >> 7, f = o & 127;
        int base = b*LL + l;
        float v = ue[(size_t)user[base]*FF + f] + pe[(size_t)poi[base]*FF + f]
                + te[tod[base]*FF + f] + de[dow[base]*FF + f];
        inT[f*28 + l] = v;
    }
    // zero the 3 pad columns (l = 25..27)
    for (int o = tid; o < FF*3; o += 384) inT[(o/3)*28 + 25 + (o%3)] = 0.f;

    // pairwise haversine / delta-t + stats
    const float rad = 0.017453292519943295f;
    const float INF = __int_as_float(0x7F800000);
    float mxs = 0.f, mns = INF, mxt = 0.f, mnt = INF;
    for (int e = tid; e < LL*LL; e += 384) {
        int i = e / LL, j = e % LL;
        float la1 = lat[b*LL+i], lo1 = lon[b*LL+i];
        float la2 = lat[b*LL+j], lo2 = lon[b*LL+j];
        float a = 0.5f - 0.5f*cosf((la2-la1)*rad)
                + cosf(la1*rad)*cosf(la2*rad)*(1.0f - cosf((lo2-lo1)*rad))*0.5f;
        float ds = 12742.0f * asinf(sqrtf(a));
        float dt = fabsf(ut[b*LL+i] - ut[b*LL+j]);
        g_ds[b*LL*LL + e] = ds;
        g_dt[b*LL*LL + e] = dt;
        mxs = fmaxf(mxs, ds); mns = fminf(mns, ds);
        mxt = fmaxf(mxt, dt); mnt = fminf(mnt, dt);
    }
    float mxi = 0.f, mni = INF;
    if (tid < LL) {
        float ti = (tid == 0) ? 0.f : fabsf(ut[b*LL+tid] - ut[b*LL+tid-1]);
        g_tint[b*LL + tid] = ti;
        mxi = ti; mni = ti;
    }
    redMax(mxs, 0); redMin(mns, 1);
    redMax(mxt, 2); redMin(mnt, 3);
    redMax(mxi, 6); redMin(mni, 7);
    __syncthreads();

    // fused QKV: each thread produces out[0..24][f] for its matrix
    int m = tid >> 7, f = tid & 127;
    const float* W  = (m == 0) ? Wq : (m == 1) ? Wk : Wv;
    const float* bp = (m == 0) ? bq : (m == 1) ? bk : bv;
    float bias = bp[f];
    unsigned long long acc[13];
    unsigned long long binit = pack2(bias, bias);
    #pragma unroll
    for (int j = 0; j < 13; ++j) acc[j] = binit;

    #pragma unroll 4
    for (int g = 0; g < FF; ++g) {
        float w = W[g*FF + f];                       // coalesced across warp
        unsigned long long w2 = pack2(w, w);
        const ulonglong2* row = (const ulonglong2*)(inT + g*28);  // broadcast
        #pragma unroll
        for (int j = 0; j < 6; ++j) {
            ulonglong2 a = row[j];                   // l = 4j .. 4j+3
            ffma2(acc[2*j],   a.x, w2);
            ffma2(acc[2*j+1], a.y, w2);
        }
        // l = 24,25 (25 is pad)
        unsigned long long a6 = ((const unsigned long long*)(inT + g*28))[12];
        ffma2(acc[12], a6, w2);
    }
    float* dst = ((m == 0) ? g_q : (m == 1) ? g_k : g_v) + (size_t)b*LL*FF;
    #pragma unroll
    for (int j = 0; j < 12; ++j) {
        dst[(2*j)*FF + f]   = lo2(acc[j]);
        dst[(2*j+1)*FF + f] = hi2(acc[j]);
    }
    dst[24*FF + f] = lo2(acc[12]);
}

// ---------------- kernel 2: scan distance_matrix[poi] for max/min --------------
__global__ void k_scan(const int* __restrict__ poi, const float* __restrict__ dist) {
    int m = blockIdx.x;
    int row = poi[m];
    const float4* d4 = (const float4*)(dist + (size_t)row * PP);
    float mx = 0.f, mn = __int_as_float(0x7F800000);
    for (int c = threadIdx.x; c < PP/4; c += blockDim.x) {
        float4 v = d4[c];
        mx = fmaxf(mx, fmaxf(fmaxf(v.x, v.y), fmaxf(v.z, v.w)));
        mn = fminf(mn, fminf(fminf(v.x, v.y), fminf(v.z, v.w)));
    }
    redMax(mx, 4); redMin(mn, 5);
}

// ---------------- kernel 3: per-batch attention --------------------------------
__global__ void k_att() {
    int b = blockIdx.x, tid = threadIdx.x;
    __shared__ float qs[LL*FF], ks[LL*FF], vs[LL*FF], aw[LL*LL];
    for (int o = tid; o < LL*FF; o += blockDim.x) {
        qs[o] = g_q[b*LL*FF + o];
        ks[o] = g_k[b*LL*FF + o];
        vs[o] = g_v[b*LL*FF + o];
    }
    __syncthreads();
    float su = __int_as_float(g_stats[0]), sl = __int_as_float(g_stats[1]);
    float tu = __int_as_float(g_stats[2]), tl = __int_as_float(g_stats[3]);
    float nis = -1.0f/(su - sl), nit = -1.0f/(tu - tl);
    for (int e = tid; e < LL*LL; e += blockDim.x) {
        int i = e / LL, j = e % LL;
        const float4* q4 = (const float4*)(qs + i*FF);
        const float4* k4 = (const float4*)(ks + j*FF);
        float s = 0.f;
        #pragma unroll
        for (int f = 0; f < FF/4; ++f) {
            float4 a = q4[f], c = k4[f];
            s += a.x*c.x + a.y*c.y + a.z*c.z + a.w*c.w;
        }
        float delta = 0.5f*(__expf(g_ds[b*LL*LL + e]*nis) + __expf(g_dt[b*LL*LL + e]*nit));
        aw[e] = s + delta;
    }
    __syncthreads();
    if (tid < LL) {
        float m = -1e30f;
        #pragma unroll
        for (int j = 0; j < LL; ++j) m = fmaxf(m, aw[tid*LL + j]);
        float tmp[LL], sum = 0.f;
        #pragma unroll
        for (int j = 0; j < LL; ++j) { float e = __expf(aw[tid*LL + j] - m); tmp[j] = e; sum += e; }
        float inv = 1.0f / sum;
        #pragma unroll
        for (int j = 0; j < LL; ++j) aw[tid*LL + j] = tmp[j] * inv;
    }
    __syncthreads();
    for (int o = tid; o < LL*FF; o += blockDim.x) {
        int i = o >> 7, f = o & 127;
        float s = 0.f;
        #pragma unroll
        for (int j = 0; j < LL; ++j) s += aw[i*LL + j] * vs[j*FF + f];
        g_attn[b*LL*FF + o] = s;
    }
}

// ---------------- kernel 4: fused candidate scoring ----------------------------
// pre[b,p] = b_val + sum_l (0.5*w_l*exp(-dist[poi_bl,p]/Ds) + 0.5*w_l*Et_bl) * <attn_bl, poi_emb_p>
// GB batches per block share one poi_emb stream; 16 warps/SM for latency hiding.
__global__ __launch_bounds__(256, 2) void k_final(
        const float* __restrict__ poi_emb, const float* __restrict__ dist,
        const int* __restrict__ poi, const float* __restrict__ w_val,
        const float* __restrict__ b_val, float* __restrict__ out, int out_size) {
    __shared__ __align__(16) float As[GB*LL*FF];
    __shared__ float sa_s[GB*LL], se_s[GB*LL];
    __shared__ size_t doff_s[GB*LL];
    int tid = threadIdx.x, bg = blockIdx.y;
    int b0 = bg*GB;
    int bn = min(GB, BB - b0);

    for (int o = tid; o < bn*LL*(FF/4); o += 256)
        ((float4*)As)[o] = ((const float4*)g_attn)[(size_t)b0*LL*(FF/4) + o];
    if (tid < bn*LL) {
        int l = tid % LL, b = b0 + tid/LL;
        doff_s[tid] = (size_t)poi[b*LL + l] * PP;
        float Dt = __int_as_float(g_stats[6]) - __int_as_float(g_stats[7]);
        float s = 0.5f * w_val[l];
        sa_s[tid] = s;
        se_s[tid] = s * __expf(-g_tint[b*LL + l] / Dt);
    }
    __syncthreads();

    int p = blockIdx.x*256 + tid;
    int pc = (p < PP) ? p : (PP-1);
    const ulonglong2* W2 = (const ulonglong2*)(poi_emb + (size_t)pc * FF);
    float nis = -1.0f / (__int_as_float(g_stats[4]) - __int_as_float(g_stats[5]));
    float bvv = b_val[0];

    for (int bi = 0; bi < bn; ++bi) {
        const ulonglong2* A2 = (const ulonglong2*)(As + bi*LL*FF);
        unsigned long long acc[LL];
        #pragma unroll
        for (int l = 0; l < LL; ++l) acc[l] = 0ull;

        #pragma unroll 4
        for (int f4 = 0; f4 < FF/4; ++f4) {
            ulonglong2 w = W2[f4];                   // streamed, MLP-4
            #pragma unroll
            for (int l = 0; l < LL; ++l) {
                ulonglong2 a = A2[l*(FF/4) + f4];    // smem broadcast
                ffma2(acc[l], a.x, w.x);
                ffma2(acc[l], a.y, w.y);
            }
        }

        // epilogue: 25 gathered dist loads with full MLP, then combine
        float dv[LL];
        #pragma unroll
        for (int l = 0; l < LL; ++l) dv[l] = dist[doff_s[bi*LL + l] + pc];
        float pre = bvv;
        #pragma unroll
        for (int l = 0; l < LL; ++l) {
            float g = lo2(acc[l]) + hi2(acc[l]);
            pre += (sa_s[bi*LL + l] * __expf(dv[l]*nis) + se_s[bi*LL + l]) * g;
        }
        if (p < PP) {
            int n = (b0 + bi)*PP + p;
            out[n] = pre;
            if (out_size >= 2*BB*PP) out[BB*PP + n] = pre;
        }
    }
}

// ---------------- launch ------------------------------------------------------
extern "C" void kernel_launch(void* const* d_in, const int* in_sizes, int n_in,
                              void* d_out, int out_size) {
    const int*   user  = (const int*)d_in[0];
    const int*   poi   = (const int*)d_in[1];
    // d_in[2] = cat (unused)
    const float* lat   = (const float*)d_in[3];
    const float* lon   = (const float*)d_in[4];
    const int*   tod   = (const int*)d_in[5];
    const int*   dow   = (const int*)d_in[6];
    const float* ut    = (const float*)d_in[7];
    const float* ue    = (const float*)d_in[8];
    const float* pe    = (const float*)d_in[9];
    const float* te    = (const float*)d_in[10];
    const float* de    = (const float*)d_in[11];
    const float* Wq    = (const float*)d_in[12];
    const float* bq    = (const float*)d_in[13];
    const float* Wk    = (const float*)d_in[14];
    const float* bk    = (const float*)d_in[15];
    const float* Wv    = (const float*)d_in[16];
    const float* bv    = (const float*)d_in[17];
    const float* w_val = (const float*)d_in[18];
    const float* b_val = (const float*)d_in[19];
    const float* dist  = (const float*)d_in[20];
    float* out = (float*)d_out;

    k_init<<<1, 32>>>();
    k_prep_qkv<<<BB, 384>>>(user, poi, tod, dow, lat, lon, ut, ue, pe, te, de,
                            Wq, bq, Wk, bk, Wv, bv);
    k_scan<<<BB*LL, 256>>>(poi, dist);
    k_att<<<BB, 256>>>();
    k_final<<<dim3((PP + 255)/256, (BB + GB - 1)/GB), 256>>>(pe, dist, poi, w_val, b_val, out, out_size);
}